// round 11
// baseline (speedup 1.0000x reference)
#include <cuda_runtime.h>
#include <cstdint>

// ===================== compile-time SH normalization =====================
constexpr double PI_D = 3.141592653589793238462643383279502884;
constexpr double cfact(int n){ return n <= 1 ? 1.0 : (double)n * cfact(n - 1); }
constexpr double csqrt_it(double x, double g, int it){ return it == 0 ? g : csqrt_it(x, 0.5*(g + x/g), it - 1); }
constexpr double csqrt_(double x){ return x <= 0.0 ? 0.0 : csqrt_it(x, x > 1.0 ? x : 1.0, 100); }
constexpr double knorm(int l, int am){
    return csqrt_((2.0*l + 1.0)/(4.0*PI_D) * cfact(l - am)/cfact(l + am))
         * (am ? csqrt_(2.0) : 1.0);
}
#define KN(l,am) ((float)knorm(l,am))
__constant__ float YN[36] = {
    KN(0,0),
    KN(1,1), KN(1,0), KN(1,1),
    KN(2,2), KN(2,1), KN(2,0), KN(2,1), KN(2,2),
    KN(3,3), KN(3,2), KN(3,1), KN(3,0), KN(3,1), KN(3,2), KN(3,3),
    KN(4,4), KN(4,3), KN(4,2), KN(4,1), KN(4,0), KN(4,1), KN(4,2), KN(4,3), KN(4,4),
    KN(5,5), KN(5,4), KN(5,3), KN(5,2), KN(5,1), KN(5,0), KN(5,1), KN(5,2), KN(5,3), KN(5,4), KN(5,5)
};

// ===================== device globals (no allocation) =====================
__device__ unsigned g_counter;   // work-stealing tile counter (reset per launch)
__device__ int      g_is64;      // 1 if pair_indices stored as int64

// ===================== f32x2 helpers =====================
__device__ __forceinline__ unsigned long long fpack2(float lo, float hi){
    unsigned long long r;
    asm("mov.b64 %0, {%1, %2};" : "=l"(r) : "f"(lo), "f"(hi));
    return r;
}
__device__ __forceinline__ void funpack2(unsigned long long v, float& lo, float& hi){
    asm("mov.b64 {%0, %1}, %2;" : "=f"(lo), "=f"(hi) : "l"(v));
}
__device__ __forceinline__ void ffma2(unsigned long long& d, unsigned long long a, unsigned long long b){
    asm("fma.rn.f32x2 %0, %1, %2, %0;" : "+l"(d) : "l"(a), "l"(b));
}

// ===================== init: reset counter + detect pair dtype =====================
__global__ void init_kernel(const unsigned* __restrict__ w, int nwords){
    __shared__ unsigned s;
    if (threadIdx.x == 0){ s = 0u; g_counter = 0u; }
    __syncthreads();
    unsigned acc = 0u;
    for (int j = 2*threadIdx.x + 1; j < nwords; j += 2*blockDim.x) acc |= w[j];
    atomicOr(&s, acc);
    __syncthreads();
    // if every sampled odd 32-bit word is zero, values are int64 (hi halves of
    // small nonneg ints); random int32 data would make this astronomically unlikely
    if (threadIdx.x == 0) g_is64 = (s == 0u) ? 1 : 0;
}

// ===================== pair_indices pass-through =====================
__global__ void copy_cast_kernel(const unsigned* __restrict__ w, float* __restrict__ dst, long long n){
    const int is64 = g_is64;
    long long i = (long long)blockIdx.x*blockDim.x + threadIdx.x;
    const long long stride = (long long)gridDim.x*blockDim.x;
    for (; i < n; i += stride)
        dst[i] = (float)(int)w[is64 ? (i << 1) : i];
}
__global__ void copy_raw_kernel(const unsigned* __restrict__ w, unsigned* __restrict__ dst, long long n){
    long long i = (long long)blockIdx.x*blockDim.x + threadIdx.x;
    const long long stride = (long long)gridDim.x*blockDim.x;
    for (; i < n; i += stride) dst[i] = w[i];
}

// ===================== main fused kernel =====================
// Tile = 128 edges. Phase 1: per-thread spherical basis (36 vals, duplicated
// into SMEM as {B,B} pairs). Phase 2: 128x64x36 register-blocked GEMM in
// packed f32x2 (8 edges x 8 cols per thread), bias-initialized accumulators,
// coalesced float4 stores.
__global__ void __launch_bounds__(128)
sph_basis_kernel(const float* __restrict__ env,
                 const float* __restrict__ Kmat,
                 const float* __restrict__ bias,
                 float* __restrict__ out,
                 int nE, int ntiles)
{
    __shared__ __align__(16) float  K2s[36*64];     // normalization-folded kernel
    __shared__ __align__(16) float2 sphs[36*128];   // duplicated basis values
    __shared__ unsigned tile_s;

    const int t  = threadIdx.x;
    const int tx = t & 7;          // column group (8 groups of 8 cols)
    const int ty = t >> 3;         // edge group   (16 groups of 8 edges)
    const int cbase = tx * 8;
    const int ebase = ty * 8;

    // fold Y_lm normalization into the kernel matrix (once per block)
    for (int idx = t; idx < 36*64; idx += 128)
        K2s[idx] = Kmat[idx] * YN[idx >> 6];

    // bias pairs for this thread's 8 columns
    unsigned long long bp[4];
#pragma unroll
    for (int p = 0; p < 4; p++)
        bp[p] = fpack2(bias[cbase + 2*p], bias[cbase + 2*p + 1]);

    for (;;) {
        if (t == 0) tile_s = atomicAdd(&g_counter, 1u);
        __syncthreads();                       // also orders K2s build / sphs reuse
        const unsigned tile = tile_s;
        if (tile >= (unsigned)ntiles) break;
        const long long base = (long long)tile * 128;

        // ---------------- phase 1: spherical harmonics basis ----------------
        {
            float B[36];
            const long long e = base + t;
            if (e < (long long)nE) {
                const float* p6 = env + e * 6;
                const float px = p6[0], py = p6[1], pz = p6[2];
                const float ex = p6[3], ey = p6[4], ez = p6[5];

                const float dot = px*ex + py*ey + pz*ez;
                const float cx = py*ez - pz*ey;
                const float cy = pz*ex - px*ez;
                const float cz = px*ey - py*ex;
                const float cr2 = cx*cx + cy*cy + cz*cz;
                const float cr  = sqrtf(cr2);
                const float r2  = dot*dot + cr2;
                float ct, st;
                if (r2 > 0.f) { const float iv = rsqrtf(r2); ct = dot*iv; st = cr*iv; }
                else          { ct = 1.f; st = 0.f; }
                // phi: edges_proj = e*cos(theta); dot_p = ez*ct; |p x e*ct| = |ct|*cr
                const float dp  = ez * ct;
                const float cpp = fabsf(ct) * cr;
                const float rp2 = dp*dp + cpp*cpp;
                float cphi, sphi;
                if (rp2 > 0.f) { const float iv = rsqrtf(rp2); cphi = dp*iv; sphi = cpp*iv; }
                else           { cphi = 1.f; sphi = 0.f; }

                // associated Legendre P[l][m] (same recurrences as reference)
                float P[6][6];
                P[0][0] = 1.f;
                float spw = st;
                P[1][1] = -spw;
                spw *= st; P[2][2] =    3.f * spw;
                spw *= st; P[3][3] =  -15.f * spw;
                spw *= st; P[4][4] =  105.f * spw;
                spw *= st; P[5][5] = -945.f * spw;
#pragma unroll
                for (int m = 0; m < 5; m++)
                    P[m+1][m] = (2.f*(float)m + 1.f) * ct * P[m][m];
#pragma unroll
                for (int m = 0; m < 6; m++)
#pragma unroll
                    for (int l = m+2; l < 6; l++)
                        P[l][m] = ((2.f*(float)l - 1.f)*ct*P[l-1][m]
                                   - (float)(l+m-1)*P[l-2][m]) * (1.f/(float)(l-m));

                // cos(m*phi), sin(m*phi) via Chebyshev recurrence
                float cm[6], sm[6];
                cm[0] = 1.f;  sm[0] = 0.f;
                cm[1] = cphi; sm[1] = sphi;
#pragma unroll
                for (int m = 2; m < 6; m++) {
                    cm[m] = cm[m-1]*cphi - sm[m-1]*sphi;
                    sm[m] = sm[m-1]*cphi + cm[m-1]*sphi;
                }
#pragma unroll
                for (int l = 0; l < 6; l++)
#pragma unroll
                    for (int m = -l; m <= l; m++) {
                        const int am = m < 0 ? -m : m;
                        const float v = (m == 0) ? P[l][0]
                                       : (m > 0 ? cm[am] : sm[am]) * P[l][am];
                        B[l*l + m + l] = v;   // normalization folded into K2s
                    }
            } else {
#pragma unroll
                for (int i = 0; i < 36; i++) B[i] = 0.f;
            }
            // duplicated store -> LDS.128 later yields b64 broadcast operands
#pragma unroll
            for (int i = 0; i < 36; i++)
                sphs[i*128 + t] = make_float2(B[i], B[i]);
        }
        __syncthreads();

        // ---------------- phase 2: 128x64x36 GEMM in f32x2 ----------------
        unsigned long long acc[8][4];
#pragma unroll
        for (int e2 = 0; e2 < 8; e2++)
#pragma unroll
            for (int p = 0; p < 4; p++)
                acc[e2][p] = bp[p];

#pragma unroll
        for (int i = 0; i < 36; i++) {
            const ulonglong2* kp = reinterpret_cast<const ulonglong2*>(K2s + i*64 + cbase);
            const ulonglong2 ka = kp[0];
            const ulonglong2 kb = kp[1];
            const ulonglong2* sp = reinterpret_cast<const ulonglong2*>(sphs + i*128 + ebase);
            const ulonglong2 sA = sp[0], sB2 = sp[1], sC = sp[2], sD = sp[3];
            const unsigned long long sd[8] = {sA.x, sA.y, sB2.x, sB2.y, sC.x, sC.y, sD.x, sD.y};
#pragma unroll
            for (int e2 = 0; e2 < 8; e2++) {
                ffma2(acc[e2][0], sd[e2], ka.x);
                ffma2(acc[e2][1], sd[e2], ka.y);
                ffma2(acc[e2][2], sd[e2], kb.x);
                ffma2(acc[e2][3], sd[e2], kb.y);
            }
        }

        // coalesced float4 stores
#pragma unroll
        for (int e2 = 0; e2 < 8; e2++) {
            const long long edge = base + ebase + e2;
            if (edge < (long long)nE) {
                float a0,a1,a2,a3,a4,a5,a6,a7;
                funpack2(acc[e2][0], a0, a1);
                funpack2(acc[e2][1], a2, a3);
                funpack2(acc[e2][2], a4, a5);
                funpack2(acc[e2][3], a6, a7);
                float4* o = reinterpret_cast<float4*>(out + edge*64 + cbase);
                o[0] = make_float4(a0,a1,a2,a3);
                o[1] = make_float4(a4,a5,a6,a7);
            }
        }
        __syncthreads();   // protect sphs before next tile's phase 1
    }
}

// ===================== launcher =====================
extern "C" void kernel_launch(void* const* d_in, const int* in_sizes, int n_in,
                              void* d_out, int out_size)
{
    const float*    env  = (const float*)d_in[0];
    const unsigned* pw   = (const unsigned*)d_in[1];   // pair_indices raw words
    const float*    Kmat = (const float*)d_in[2];
    const float*    bias = (const float*)d_in[3];
    float*          outf = (float*)d_out;

    const long long nE     = (long long)in_sizes[0] / 6;
    const int       ntiles = (int)((nE + 127) / 128);
    const long long osz    = (long long)out_size;

    int nwords = (int)(2*nE < 4096 ? 2*nE : 4096);
    init_kernel<<<1, 256>>>(pw, nwords);

    int blocks = ntiles < 592 ? ntiles : 592;   // 148 SMs x ~4 blocks, work-stealing
    sph_basis_kernel<<<blocks, 128>>>(env, Kmat, bias, outf, (int)nE, ntiles);

    if (osz == 66*nE) {
        // float32 concat: [out (nE*64) | pair_indices cast to float (nE*2)]
        const long long n2 = 2*nE;
        int cb = (int)((n2 + 255) / 256); if (cb > 4096) cb = 4096;
        copy_cast_kernel<<<cb, 256>>>(pw, outf + 64*nE, n2);
    } else if (osz == 68*nE) {
        // raw int64 bits appended after the float region
        const long long n4 = 4*nE;
        copy_raw_kernel<<<4096, 256>>>(pw, (unsigned*)outf + 64*nE, n4);
    }
    // osz == 64*nE: output is just the projection; nothing else to write
}

// round 12
// speedup vs baseline: 1.0048x; 1.0048x over previous
#include <cuda_runtime.h>
#include <cstdint>

// ===================== compile-time SH normalization =====================
constexpr double PI_D = 3.141592653589793238462643383279502884;
constexpr double cfact(int n){ return n <= 1 ? 1.0 : (double)n * cfact(n - 1); }
constexpr double csqrt_it(double x, double g, int it){ return it == 0 ? g : csqrt_it(x, 0.5*(g + x/g), it - 1); }
constexpr double csqrt_(double x){ return x <= 0.0 ? 0.0 : csqrt_it(x, x > 1.0 ? x : 1.0, 100); }
constexpr double knorm(int l, int am){
    return csqrt_((2.0*l + 1.0)/(4.0*PI_D) * cfact(l - am)/cfact(l + am))
         * (am ? csqrt_(2.0) : 1.0);
}
#define KN(l,am) ((float)knorm(l,am))
__constant__ float YN[36] = {
    KN(0,0),
    KN(1,1), KN(1,0), KN(1,1),
    KN(2,2), KN(2,1), KN(2,0), KN(2,1), KN(2,2),
    KN(3,3), KN(3,2), KN(3,1), KN(3,0), KN(3,1), KN(3,2), KN(3,3),
    KN(4,4), KN(4,3), KN(4,2), KN(4,1), KN(4,0), KN(4,1), KN(4,2), KN(4,3), KN(4,4),
    KN(5,5), KN(5,4), KN(5,3), KN(5,2), KN(5,1), KN(5,0), KN(5,1), KN(5,2), KN(5,3), KN(5,4), KN(5,5)
};

// ===================== device globals (no allocation) =====================
__device__ unsigned g_counter;   // work-stealing tile counter (reset per launch)
__device__ int      g_is64;      // 1 if pair_indices stored as int64

// ===================== f32x2 helpers =====================
__device__ __forceinline__ unsigned long long fpack2(float lo, float hi){
    unsigned long long r;
    asm("mov.b64 %0, {%1, %2};" : "=l"(r) : "f"(lo), "f"(hi));
    return r;
}
__device__ __forceinline__ void funpack2(unsigned long long v, float& lo, float& hi){
    asm("mov.b64 {%0, %1}, %2;" : "=f"(lo), "=f"(hi) : "l"(v));
}
__device__ __forceinline__ void ffma2(unsigned long long& d, unsigned long long a, unsigned long long b){
    asm("fma.rn.f32x2 %0, %1, %2, %0;" : "+l"(d) : "l"(a), "l"(b));
}

// ===================== init: reset counter + detect pair dtype =====================
__global__ void init_kernel(const unsigned* __restrict__ w, int nwords){
    __shared__ unsigned s;
    if (threadIdx.x == 0){ s = 0u; g_counter = 0u; }
    __syncthreads();
    unsigned acc = 0u;
    for (int j = 2*threadIdx.x + 1; j < nwords; j += 2*blockDim.x) acc |= w[j];
    atomicOr(&s, acc);
    __syncthreads();
    // if every sampled odd 32-bit word is zero, values are int64 (hi halves of
    // small nonneg ints); random int32 data would make this astronomically unlikely
    if (threadIdx.x == 0) g_is64 = (s == 0u) ? 1 : 0;
}

// ===================== pair_indices pass-through =====================
__global__ void copy_cast_kernel(const unsigned* __restrict__ w, float* __restrict__ dst, long long n){
    const int is64 = g_is64;
    long long i = (long long)blockIdx.x*blockDim.x + threadIdx.x;
    const long long stride = (long long)gridDim.x*blockDim.x;
    for (; i < n; i += stride)
        dst[i] = (float)(int)w[is64 ? (i << 1) : i];
}
__global__ void copy_raw_kernel(const unsigned* __restrict__ w, unsigned* __restrict__ dst, long long n){
    long long i = (long long)blockIdx.x*blockDim.x + threadIdx.x;
    const long long stride = (long long)gridDim.x*blockDim.x;
    for (; i < n; i += stride) dst[i] = w[i];
}

// ===================== main fused kernel =====================
// Tile = 128 edges. Phase 1: per-thread spherical basis (36 vals, duplicated
// into SMEM as {B,B} pairs). Phase 2: 128x64x36 register-blocked GEMM in
// packed f32x2 (8 edges x 8 cols per thread), bias-initialized accumulators,
// coalesced float4 stores.
__global__ void __launch_bounds__(128)
sph_basis_kernel(const float* __restrict__ env,
                 const float* __restrict__ Kmat,
                 const float* __restrict__ bias,
                 float* __restrict__ out,
                 int nE, int ntiles)
{
    __shared__ __align__(16) float  K2s[36*64];     // normalization-folded kernel
    __shared__ __align__(16) float2 sphs[36*128];   // duplicated basis values
    __shared__ unsigned tile_s;

    const int t  = threadIdx.x;
    const int tx = t & 7;          // column group (8 groups of 8 cols)
    const int ty = t >> 3;         // edge group   (16 groups of 8 edges)
    const int cbase = tx * 8;
    const int ebase = ty * 8;

    // fold Y_lm normalization into the kernel matrix (once per block)
    for (int idx = t; idx < 36*64; idx += 128)
        K2s[idx] = Kmat[idx] * YN[idx >> 6];

    // bias pairs for this thread's 8 columns
    unsigned long long bp[4];
#pragma unroll
    for (int p = 0; p < 4; p++)
        bp[p] = fpack2(bias[cbase + 2*p], bias[cbase + 2*p + 1]);

    for (;;) {
        if (t == 0) tile_s = atomicAdd(&g_counter, 1u);
        __syncthreads();                       // also orders K2s build / sphs reuse
        const unsigned tile = tile_s;
        if (tile >= (unsigned)ntiles) break;
        const long long base = (long long)tile * 128;

        // ---------------- phase 1: spherical harmonics basis ----------------
        {
            float B[36];
            const long long e = base + t;
            if (e < (long long)nE) {
                const float* p6 = env + e * 6;
                const float px = p6[0], py = p6[1], pz = p6[2];
                const float ex = p6[3], ey = p6[4], ez = p6[5];

                const float dot = px*ex + py*ey + pz*ez;
                const float cx = py*ez - pz*ey;
                const float cy = pz*ex - px*ez;
                const float cz = px*ey - py*ex;
                const float cr2 = cx*cx + cy*cy + cz*cz;
                const float cr  = sqrtf(cr2);
                const float r2  = dot*dot + cr2;
                float ct, st;
                if (r2 > 0.f) { const float iv = rsqrtf(r2); ct = dot*iv; st = cr*iv; }
                else          { ct = 1.f; st = 0.f; }
                // phi: edges_proj = e*cos(theta); dot_p = ez*ct; |p x e*ct| = |ct|*cr
                const float dp  = ez * ct;
                const float cpp = fabsf(ct) * cr;
                const float rp2 = dp*dp + cpp*cpp;
                float cphi, sphi;
                if (rp2 > 0.f) { const float iv = rsqrtf(rp2); cphi = dp*iv; sphi = cpp*iv; }
                else           { cphi = 1.f; sphi = 0.f; }

                // associated Legendre P[l][m] (same recurrences as reference)
                float P[6][6];
                P[0][0] = 1.f;
                float spw = st;
                P[1][1] = -spw;
                spw *= st; P[2][2] =    3.f * spw;
                spw *= st; P[3][3] =  -15.f * spw;
                spw *= st; P[4][4] =  105.f * spw;
                spw *= st; P[5][5] = -945.f * spw;
#pragma unroll
                for (int m = 0; m < 5; m++)
                    P[m+1][m] = (2.f*(float)m + 1.f) * ct * P[m][m];
#pragma unroll
                for (int m = 0; m < 6; m++)
#pragma unroll
                    for (int l = m+2; l < 6; l++)
                        P[l][m] = ((2.f*(float)l - 1.f)*ct*P[l-1][m]
                                   - (float)(l+m-1)*P[l-2][m]) * (1.f/(float)(l-m));

                // cos(m*phi), sin(m*phi) via Chebyshev recurrence
                float cm[6], sm[6];
                cm[0] = 1.f;  sm[0] = 0.f;
                cm[1] = cphi; sm[1] = sphi;
#pragma unroll
                for (int m = 2; m < 6; m++) {
                    cm[m] = cm[m-1]*cphi - sm[m-1]*sphi;
                    sm[m] = sm[m-1]*cphi + cm[m-1]*sphi;
                }
#pragma unroll
                for (int l = 0; l < 6; l++)
#pragma unroll
                    for (int m = -l; m <= l; m++) {
                        const int am = m < 0 ? -m : m;
                        const float v = (m == 0) ? P[l][0]
                                       : (m > 0 ? cm[am] : sm[am]) * P[l][am];
                        B[l*l + m + l] = v;   // normalization folded into K2s
                    }
            } else {
#pragma unroll
                for (int i = 0; i < 36; i++) B[i] = 0.f;
            }
            // duplicated store -> LDS.128 later yields b64 broadcast operands
#pragma unroll
            for (int i = 0; i < 36; i++)
                sphs[i*128 + t] = make_float2(B[i], B[i]);
        }
        __syncthreads();

        // ---------------- phase 2: 128x64x36 GEMM in f32x2 ----------------
        unsigned long long acc[8][4];
#pragma unroll
        for (int e2 = 0; e2 < 8; e2++)
#pragma unroll
            for (int p = 0; p < 4; p++)
                acc[e2][p] = bp[p];

#pragma unroll
        for (int i = 0; i < 36; i++) {
            const ulonglong2* kp = reinterpret_cast<const ulonglong2*>(K2s + i*64 + cbase);
            const ulonglong2 ka = kp[0];
            const ulonglong2 kb = kp[1];
            const ulonglong2* sp = reinterpret_cast<const ulonglong2*>(sphs + i*128 + ebase);
            const ulonglong2 sA = sp[0], sB2 = sp[1], sC = sp[2], sD = sp[3];
            const unsigned long long sd[8] = {sA.x, sA.y, sB2.x, sB2.y, sC.x, sC.y, sD.x, sD.y};
#pragma unroll
            for (int e2 = 0; e2 < 8; e2++) {
                ffma2(acc[e2][0], sd[e2], ka.x);
                ffma2(acc[e2][1], sd[e2], ka.y);
                ffma2(acc[e2][2], sd[e2], kb.x);
                ffma2(acc[e2][3], sd[e2], kb.y);
            }
        }

        // coalesced float4 stores
#pragma unroll
        for (int e2 = 0; e2 < 8; e2++) {
            const long long edge = base + ebase + e2;
            if (edge < (long long)nE) {
                float a0,a1,a2,a3,a4,a5,a6,a7;
                funpack2(acc[e2][0], a0, a1);
                funpack2(acc[e2][1], a2, a3);
                funpack2(acc[e2][2], a4, a5);
                funpack2(acc[e2][3], a6, a7);
                float4* o = reinterpret_cast<float4*>(out + edge*64 + cbase);
                o[0] = make_float4(a0,a1,a2,a3);
                o[1] = make_float4(a4,a5,a6,a7);
            }
        }
        __syncthreads();   // protect sphs before next tile's phase 1
    }
}

// ===================== launcher =====================
extern "C" void kernel_launch(void* const* d_in, const int* in_sizes, int n_in,
                              void* d_out, int out_size)
{
    const float*    env  = (const float*)d_in[0];
    const unsigned* pw   = (const unsigned*)d_in[1];   // pair_indices raw words
    const float*    Kmat = (const float*)d_in[2];
    const float*    bias = (const float*)d_in[3];
    float*          outf = (float*)d_out;

    const long long nE     = (long long)in_sizes[0] / 6;
    const int       ntiles = (int)((nE + 127) / 128);
    const long long osz    = (long long)out_size;

    int nwords = (int)(2*nE < 4096 ? 2*nE : 4096);
    init_kernel<<<1, 256>>>(pw, nwords);

    int blocks = ntiles < 592 ? ntiles : 592;   // 148 SMs x ~4 blocks, work-stealing
    sph_basis_kernel<<<blocks, 128>>>(env, Kmat, bias, outf, (int)nE, ntiles);

    if (osz == 66*nE) {
        // float32 concat: [out (nE*64) | pair_indices cast to float (nE*2)]
        const long long n2 = 2*nE;
        int cb = (int)((n2 + 255) / 256); if (cb > 4096) cb = 4096;
        copy_cast_kernel<<<cb, 256>>>(pw, outf + 64*nE, n2);
    } else if (osz == 68*nE) {
        // raw int64 bits appended after the float region
        const long long n4 = 4*nE;
        copy_raw_kernel<<<4096, 256>>>(pw, (unsigned*)outf + 64*nE, n4);
    }
    // osz == 64*nE: output is just the projection; nothing else to write
}